// round 2
// baseline (speedup 1.0000x reference)
#include <cuda_runtime.h>
#include <math.h>

#define Nn 8192
#define Ee 131072
#define C0 64
#define C1 32
#define NSs 160     // 2*C0 + C1
#define NVv 128     // C0 + 2*C1
#define EPB 8       // edges per warp batch

// ---------------- static device scratch ----------------
__device__ float g_s[Nn * C0];
__device__ float g_v[Nn * C1 * 3];
__device__ float g_skip_s[Nn * C0];
__device__ float g_skip_v[Nn * C1 * 3];
__device__ float g_agg_s[Nn * NSs];
__device__ float g_agg_v[Nn * NVv * 3];

__device__ __forceinline__ float silu_f(float x) {
    return __fdividef(x, 1.0f + __expf(-x));
}

// ---------------- kernel 0: zero aggregation buffers ----------------
__global__ void zero_agg_kernel() {
    long i = (long)blockIdx.x * blockDim.x + threadIdx.x;
    long stride = (long)gridDim.x * blockDim.x;
    float4* a = (float4*)g_agg_s;
    long na = (long)Nn * NSs / 4;
    for (long j = i; j < na; j += stride) a[j] = make_float4(0.f, 0.f, 0.f, 0.f);
    float4* b = (float4*)g_agg_v;
    long nb = (long)Nn * NVv * 3 / 4;
    for (long j = i; j < nb; j += stride) b[j] = make_float4(0.f, 0.f, 0.f, 0.f);
}

// ---------------- kernel 1: node pre (Wu0/Wu1 + skips) ----------------
__global__ void __launch_bounds__(256) node_pre_kernel(
    const float* __restrict__ s_in, const float* __restrict__ v_in,
    const int* __restrict__ species,
    const float* __restrict__ Wskip0, const float* __restrict__ Wskip1,
    const float* __restrict__ Wu0, const float* __restrict__ Wu1)
{
    extern __shared__ float sm[];
    float* sWu0 = sm;                  // 4096
    float* sWu1 = sWu0 + 4096;         // 1024
    float* sWs0 = sWu1 + 1024;         // 16384
    float* sWs1 = sWs0 + 16384;        // 4096
    float* bufs = sWs1 + 4096;         // 8 warps * 160

    int tid = threadIdx.x;
    for (int i = tid; i < 4096;  i += blockDim.x) sWu0[i] = Wu0[i];
    for (int i = tid; i < 1024;  i += blockDim.x) sWu1[i] = Wu1[i];
    for (int i = tid; i < 16384; i += blockDim.x) sWs0[i] = Wskip0[i];
    for (int i = tid; i < 4096;  i += blockDim.x) sWs1[i] = Wskip1[i];
    __syncthreads();

    int w = tid >> 5, lane = tid & 31;
    float* sb = bufs + w * 160;
    float* vb = sb + 64;
    int warpsTotal = gridDim.x * 8;

    for (int n = blockIdx.x * 8 + w; n < Nn; n += warpsTotal) {
        sb[lane]      = s_in[n * 64 + lane];
        sb[lane + 32] = s_in[n * 64 + lane + 32];
        vb[lane]      = v_in[n * 96 + lane];
        vb[lane + 32] = v_in[n * 96 + lane + 32];
        vb[lane + 64] = v_in[n * 96 + lane + 64];
        __syncwarp();
        int sp = species[n];
        const float* Ws0 = sWs0 + sp * 4096;
        const float* Ws1 = sWs1 + sp * 1024;

        float a0 = 0.f, a1 = 0.f, b0 = 0.f, b1 = 0.f;
        #pragma unroll 8
        for (int c = 0; c < 64; c++) {
            float x = sb[c];
            a0 = fmaf(x, sWu0[c * 64 + lane],      a0);
            a1 = fmaf(x, sWu0[c * 64 + lane + 32], a1);
            b0 = fmaf(x, Ws0[c * 64 + lane],       b0);
            b1 = fmaf(x, Ws0[c * 64 + lane + 32],  b1);
        }
        g_s[n * 64 + lane]      = a0;
        g_s[n * 64 + lane + 32] = a1;
        g_skip_s[n * 64 + lane]      = b0;
        g_skip_s[n * 64 + lane + 32] = b1;

        float u0 = 0.f, u1 = 0.f, u2 = 0.f, k0 = 0.f, k1 = 0.f, k2 = 0.f;
        #pragma unroll 8
        for (int c = 0; c < 32; c++) {
            float wu = sWu1[c * 32 + lane];
            float wk = Ws1[c * 32 + lane];
            float x0 = vb[c * 3], x1 = vb[c * 3 + 1], x2 = vb[c * 3 + 2];
            u0 = fmaf(x0, wu, u0); u1 = fmaf(x1, wu, u1); u2 = fmaf(x2, wu, u2);
            k0 = fmaf(x0, wk, k0); k1 = fmaf(x1, wk, k1); k2 = fmaf(x2, wk, k2);
        }
        g_v[n * 96 + lane * 3]     = u0;
        g_v[n * 96 + lane * 3 + 1] = u1;
        g_v[n * 96 + lane * 3 + 2] = u2;
        g_skip_v[n * 96 + lane * 3]     = k0;
        g_skip_v[n * 96 + lane * 3 + 1] = k1;
        g_skip_v[n * 96 + lane * 3 + 2] = k2;
        __syncwarp();
    }
}

// ---------------- kernel 2: fused edge MLP + messages + vector-red scatter ----------------
__global__ void __launch_bounds__(384) edge_kernel(
    const float* __restrict__ radial, const float* __restrict__ Y0,
    const float* __restrict__ Y1,
    const int* __restrict__ senders, const int* __restrict__ receivers,
    const float* __restrict__ Wm1, const float* __restrict__ Wm2,
    const float* __restrict__ Wm3)
{
    extern __shared__ float sm[];
    float* sWm1 = sm;                 // 512
    float* sWm2 = sWm1 + 512;         // 4096
    float* sWm3 = sWm2 + 4096;        // 18432
    float* wb   = sWm3 + 18432;

    int tid = threadIdx.x, w = tid >> 5, lane = tid & 31;
    for (int i = tid; i < 512;   i += blockDim.x) sWm1[i] = Wm1[i];
    for (int i = tid; i < 4096;  i += blockDim.x) sWm2[i] = Wm2[i];
    for (int i = tid; i < 18432; i += blockDim.x) sWm3[i] = Wm3[i];
    __syncthreads();

    const int perW = EPB * 64 * 2 + 544;
    float* h1b = wb + w * perW;
    float* h2b = h1b + EPB * 64;
    float* msg = h2b + EPB * 64;

    int nwarps = gridDim.x * 12;
    int gw = blockIdx.x * 12 + w;
    const float inv_s3 = 0.57735026918962576f;

    for (int e0 = gw * EPB; e0 < Ee; e0 += nwarps * EPB) {
        // layer 1
        #pragma unroll
        for (int t = 0; t < EPB; t++) {
            int e = e0 + t;
            float rv = (lane < 8) ? radial[e * 8 + lane] : 0.f;
            float a0 = 0.f, a1 = 0.f;
            #pragma unroll
            for (int k = 0; k < 8; k++) {
                float rk = __shfl_sync(0xffffffffu, rv, k);
                a0 = fmaf(rk, sWm1[k * 64 + lane],      a0);
                a1 = fmaf(rk, sWm1[k * 64 + lane + 32], a1);
            }
            h1b[t * 64 + lane]      = silu_f(a0);
            h1b[t * 64 + lane + 32] = silu_f(a1);
        }
        __syncwarp();

        // layer 2
        {
            float acc0[EPB], acc1[EPB];
            #pragma unroll
            for (int t = 0; t < EPB; t++) { acc0[t] = 0.f; acc1[t] = 0.f; }
            for (int k = 0; k < 64; k++) {
                float w0 = sWm2[k * 64 + lane];
                float w1 = sWm2[k * 64 + lane + 32];
                #pragma unroll
                for (int t = 0; t < EPB; t++) {
                    float hk = h1b[t * 64 + k];
                    acc0[t] = fmaf(hk, w0, acc0[t]);
                    acc1[t] = fmaf(hk, w1, acc1[t]);
                }
            }
            #pragma unroll
            for (int t = 0; t < EPB; t++) {
                h2b[t * 64 + lane]      = silu_f(acc0[t]);
                h2b[t * 64 + lane + 32] = silu_f(acc1[t]);
            }
        }
        __syncwarp();

        // layer 3: lane owns mix columns lane+32r, r=0..8
        float macc[EPB][9];
        #pragma unroll
        for (int t = 0; t < EPB; t++)
            #pragma unroll
            for (int r = 0; r < 9; r++) macc[t][r] = 0.f;

        for (int k = 0; k < 64; k++) {
            float wv[9];
            #pragma unroll
            for (int r = 0; r < 9; r++) wv[r] = sWm3[k * 288 + lane + 32 * r];
            #pragma unroll
            for (int t = 0; t < EPB; t++) {
                float hk = h2b[t * 64 + k];
                #pragma unroll
                for (int r = 0; r < 9; r++) macc[t][r] = fmaf(hk, wv[r], macc[t][r]);
            }
        }

        // messages + scatter
        #pragma unroll
        for (int t = 0; t < EPB; t++) {
            int e = e0 + t;
            int snd = senders[e];
            int rcv = receivers[e];
            float m0  = g_s[snd * 64 + lane];
            float m1  = g_s[snd * 64 + lane + 32];
            float mv0 = g_v[snd * 96 + lane * 3];
            float mv1 = g_v[snd * 96 + lane * 3 + 1];
            float mv2 = g_v[snd * 96 + lane * 3 + 2];
            float y0  = Y0[e];
            float y10 = Y1[e * 3], y11 = Y1[e * 3 + 1], y12 = Y1[e * 3 + 2];
            float dot = (mv0 * y10 + mv1 * y11 + mv2 * y12) * inv_s3;

            msg[lane]       = m0 * macc[t][0];
            msg[32 + lane]  = m1 * macc[t][1];
            msg[64 + lane]  = m0 * y0 * macc[t][2];
            msg[96 + lane]  = m1 * y0 * macc[t][3];
            msg[128 + lane] = dot * macc[t][4];
            int b0 = 160 + lane * 3;
            msg[b0]     = mv0 * macc[t][5];
            msg[b0 + 1] = mv1 * macc[t][5];
            msg[b0 + 2] = mv2 * macc[t][5];
            int b1 = 160 + (32 + lane) * 3;
            float f6 = m0 * macc[t][6];
            msg[b1]     = f6 * y10;
            msg[b1 + 1] = f6 * y11;
            msg[b1 + 2] = f6 * y12;
            int b2 = 160 + (64 + lane) * 3;
            float f7 = m1 * macc[t][7];
            msg[b2]     = f7 * y10;
            msg[b2 + 1] = f7 * y11;
            msg[b2 + 2] = f7 * y12;
            int b3 = 160 + (96 + lane) * 3;
            float f8 = y0 * macc[t][8];
            msg[b3]     = mv0 * f8;
            msg[b3 + 1] = mv1 * f8;
            msg[b3 + 2] = mv2 * f8;
            __syncwarp();

            float* aggs = g_agg_s + (long)rcv * NSs;
            float* aggv = g_agg_v + (long)rcv * (NVv * 3);
            const float4* m4 = (const float4*)msg;
            #pragma unroll
            for (int gi = 0; gi < 5; gi++) {
                int g = lane + gi * 32;
                if (g < 136) {
                    float4 vv = m4[g];
                    float* p = (g < 40) ? (aggs + 4 * g) : (aggv + 4 * (g - 40));
                    asm volatile("red.global.add.v4.f32 [%0], {%1, %2, %3, %4};"
                                 :: "l"(p), "f"(vv.x), "f"(vv.y), "f"(vv.z), "f"(vv.w)
                                 : "memory");
                }
            }
            __syncwarp();
        }
    }
}

// ---------------- kernel 3: node post (Wd, tensor product, skips, quantum head) ----------------
__global__ void __launch_bounds__(256) node_post_kernel(
    const float* __restrict__ x_node,
    const float* __restrict__ Wd0, const float* __restrict__ Wd1,
    const float* __restrict__ Wt0, const float* __restrict__ Wt1,
    const float* __restrict__ Wq,  const float* __restrict__ wqml,
    const float* __restrict__ Wo,  const float* __restrict__ bo,
    float* __restrict__ out0, float* __restrict__ outS, float* __restrict__ outV)
{
    extern __shared__ float sm[];
    float* sWd0 = sm;                  // 10240
    float* sWd1 = sWd0 + 10240;        // 4096
    float* sWt0 = sWd1 + 4096;         // 16384
    float* sWt1 = sWt0 + 16384;        // 4096
    float* sWq  = sWt1 + 4096;         // 512
    float* cw   = sWq  + 512;          // 24
    float* sw_  = cw   + 24;           // 24
    float* sWo  = sw_  + 24;           // 8
    float* bufs = sWo  + 8;            // 8 warps * 712

    int tid = threadIdx.x;
    for (int i = tid; i < 10240; i += blockDim.x) sWd0[i] = Wd0[i];
    for (int i = tid; i < 4096;  i += blockDim.x) sWd1[i] = Wd1[i];
    for (int i = tid; i < 16384; i += blockDim.x) sWt0[i] = Wt0[i];
    for (int i = tid; i < 4096;  i += blockDim.x) sWt1[i] = Wt1[i];
    for (int i = tid; i < 512;   i += blockDim.x) sWq[i]  = Wq[i];
    if (tid < 24) {
        float ang = 0.5f * wqml[tid];
        cw[tid]  = cosf(ang);
        sw_[tid] = sinf(ang);
    }
    if (tid < 8) sWo[tid] = Wo[tid];
    __syncthreads();

    int w = tid >> 5, lane = tid & 31;
    float* asr  = bufs + w * 712;   // 160
    float* avr  = asr + 160;        // 384
    float* srow = avr + 384;        // 64
    float* vrow = srow + 64;        // 96
    float* frow = vrow + 96;        // 8
    const float inv16 = 1.0f / 16.0f;
    float bo0 = bo[0];
    int warpsTotal = gridDim.x * 8;

    for (int n = blockIdx.x * 8 + w; n < Nn; n += warpsTotal) {
        #pragma unroll
        for (int i = 0; i < 5; i++)  asr[lane + 32 * i] = g_agg_s[(long)n * 160 + lane + 32 * i];
        #pragma unroll
        for (int i = 0; i < 12; i++) avr[lane + 32 * i] = g_agg_v[(long)n * 384 + lane + 32 * i];
        __syncwarp();

        // s1 = agg_s @ Wd0 / 16
        float s1a = 0.f, s1b = 0.f;
        #pragma unroll 4
        for (int c = 0; c < 160; c++) {
            float x = asr[c];
            s1a = fmaf(x, sWd0[c * 64 + lane],      s1a);
            s1b = fmaf(x, sWd0[c * 64 + lane + 32], s1b);
        }
        s1a *= inv16; s1b *= inv16;

        // v1 = agg_v @ Wd1 / 16
        float v10 = 0.f, v11 = 0.f, v12 = 0.f;
        #pragma unroll 4
        for (int c = 0; c < 128; c++) {
            float wv = sWd1[c * 32 + lane];
            v10 = fmaf(avr[c * 3],     wv, v10);
            v11 = fmaf(avr[c * 3 + 1], wv, v11);
            v12 = fmaf(avr[c * 3 + 2], wv, v12);
        }
        v10 *= inv16; v11 *= inv16; v12 *= inv16;

        srow[lane] = s1a; srow[lane + 32] = s1b;
        vrow[lane * 3] = v10; vrow[lane * 3 + 1] = v11; vrow[lane * 3 + 2] = v12;
        __syncwarp();

        float xv[4];
        #pragma unroll
        for (int a = 0; a < 4; a++) xv[a] = x_node[n * 4 + a];

        // s2 = (x ⊗ s1) @ Wt0
        float o0 = 0.f, o1 = 0.f;
        #pragma unroll
        for (int a = 0; a < 4; a++) {
            float xa = xv[a];
            #pragma unroll 4
            for (int c = 0; c < 64; c++) {
                float f = xa * srow[c];
                o0 = fmaf(f, sWt0[(a * 64 + c) * 64 + lane],      o0);
                o1 = fmaf(f, sWt0[(a * 64 + c) * 64 + lane + 32], o1);
            }
        }
        // v2 = (x ⊗ v1) @ Wt1
        float p0 = 0.f, p1 = 0.f, p2 = 0.f;
        #pragma unroll
        for (int a = 0; a < 4; a++) {
            float xa = xv[a];
            #pragma unroll 4
            for (int c = 0; c < 32; c++) {
                float wt = sWt1[(a * 32 + c) * 32 + lane];
                p0 = fmaf(xa * vrow[c * 3],     wt, p0);
                p1 = fmaf(xa * vrow[c * 3 + 1], wt, p1);
                p2 = fmaf(xa * vrow[c * 3 + 2], wt, p2);
            }
        }

        float sf0 = o0 + g_skip_s[n * 64 + lane];
        float sf1 = o1 + g_skip_s[n * 64 + lane + 32];
        outS[n * 64 + lane]      = sf0;
        outS[n * 64 + lane + 32] = sf1;
        outV[n * 96 + lane * 3]     = p0 + g_skip_v[n * 96 + lane * 3];
        outV[n * 96 + lane * 3 + 1] = p1 + g_skip_v[n * 96 + lane * 3 + 1];
        outV[n * 96 + lane * 3 + 2] = p2 + g_skip_v[n * 96 + lane * 3 + 2];

        // feats = s_final @ Wq
        __syncwarp();
        srow[lane] = sf0; srow[lane + 32] = sf1;
        __syncwarp();
        if (lane < 8) {
            float f = 0.f;
            #pragma unroll 8
            for (int c = 0; c < 64; c++) f = fmaf(srow[c], sWq[c * 8 + lane], f);
            frow[lane] = f;
        }
        __syncwarp();

        // ---- quantum circuit: idx = lane*8 + l; qubit q <-> idx bit (7-q) ----
        float cs[8], sn[8];
        #pragma unroll
        for (int q = 0; q < 8; q++) {
            float a = 0.5f * frow[q];
            __sincosf(a, &sn[q], &cs[q]);
        }
        float lf = 1.f;
        #pragma unroll
        for (int j = 0; j < 5; j++) {           // lane bit j <-> idx bit 3+j <-> qubit 4-j
            int q = 4 - j;
            lf *= ((lane >> j) & 1) ? sn[q] : cs[q];
        }
        float amp[8];
        #pragma unroll
        for (int l = 0; l < 8; l++) {
            float f = lf;
            f *= (l & 4) ? sn[5] : cs[5];
            f *= (l & 2) ? sn[6] : cs[6];
            f *= (l & 1) ? sn[7] : cs[7];
            amp[l] = f;
        }

        #pragma unroll
        for (int L = 0; L < 3; L++) {
            // RY layer
            #pragma unroll
            for (int q = 0; q < 8; q++) {
                float c = cw[L * 8 + q], s = sw_[L * 8 + q];
                const int b = 7 - q;
                if (b >= 3) {
                    const int m = 1 << (b - 3);
                    int bit = (lane >> (b - 3)) & 1;
                    #pragma unroll
                    for (int l = 0; l < 8; l++) {
                        float p = __shfl_xor_sync(0xffffffffu, amp[l], m);
                        amp[l] = bit ? fmaf(s, p, c * amp[l]) : (c * amp[l] - s * p);
                    }
                } else {
                    const int tm = 1 << b;
                    #pragma unroll
                    for (int l = 0; l < 8; l++) {
                        if (!(l & tm)) {
                            float a0 = amp[l], a1 = amp[l | tm];
                            amp[l]      = c * a0 - s * a1;
                            amp[l | tm] = fmaf(s, a0, c * a1);
                        }
                    }
                }
            }
            // CNOT ring q -> (q+1)%8
            #pragma unroll
            for (int q = 0; q < 8; q++) {
                const int bc = 7 - q;
                const int bt = 7 - ((q + 1) & 7);
                if (bt >= 3) {
                    const int m = 1 << (bt - 3);
                    #pragma unroll
                    for (int l = 0; l < 8; l++) {
                        float p = __shfl_xor_sync(0xffffffffu, amp[l], m);
                        int ctrl = (bc >= 3) ? ((lane >> (bc - 3)) & 1) : ((l >> bc) & 1);
                        amp[l] = ctrl ? p : amp[l];
                    }
                } else {
                    const int tm = 1 << bt;
                    if (bc >= 3) {
                        int ctrl = (lane >> (bc - 3)) & 1;
                        #pragma unroll
                        for (int l = 0; l < 8; l++) {
                            if (!(l & tm)) {
                                float a = amp[l], bb = amp[l | tm];
                                amp[l]      = ctrl ? bb : a;
                                amp[l | tm] = ctrl ? a : bb;
                            }
                        }
                    } else {
                        #pragma unroll
                        for (int l = 0; l < 8; l++) {
                            if (!(l & tm) && ((l >> bc) & 1)) {
                                float tmp = amp[l];
                                amp[l] = amp[l | tm];
                                amp[l | tm] = tmp;
                            }
                        }
                    }
                }
            }
        }

        // Z expectations folded directly into out = z @ Wo + bo
        float tsum = 0.f, tb0 = 0.f, tb1 = 0.f, tb2 = 0.f;
        #pragma unroll
        for (int l = 0; l < 8; l++) {
            float p = amp[l] * amp[l];
            tsum += p;
            tb0 += (l & 1) ? -p : p;   // qubit 7
            tb1 += (l & 2) ? -p : p;   // qubit 6
            tb2 += (l & 4) ? -p : p;   // qubit 5
        }
        float lanesum = 0.f;
        #pragma unroll
        for (int q = 0; q < 5; q++) {  // qubits 0..4 <-> lane bit (4-q)
            float sgn = ((lane >> (4 - q)) & 1) ? -1.f : 1.f;
            lanesum = fmaf(sgn * sWo[q], 1.f, lanesum);
        }
        float op = sWo[7] * tb0 + sWo[6] * tb1 + sWo[5] * tb2 + tsum * lanesum;
        #pragma unroll
        for (int o = 16; o > 0; o >>= 1)
            op += __shfl_xor_sync(0xffffffffu, op, o);
        if (lane == 0) out0[n] = op + bo0;
        __syncwarp();
    }
}

// ---------------- launch ----------------
extern "C" void kernel_launch(void* const* d_in, const int* in_sizes, int n_in,
                              void* d_out, int out_size) {
    const float* s_in     = (const float*)d_in[0];
    const float* v_in     = (const float*)d_in[1];
    const float* x_node   = (const float*)d_in[2];
    const float* radial   = (const float*)d_in[3];
    const float* Y0       = (const float*)d_in[4];
    const float* Y1       = (const float*)d_in[5];
    const int*   species  = (const int*)d_in[6];
    const int*   senders  = (const int*)d_in[7];
    const int*   receivers= (const int*)d_in[8];
    const float* Wskip0   = (const float*)d_in[9];
    const float* Wskip1   = (const float*)d_in[10];
    const float* Wu0      = (const float*)d_in[11];
    const float* Wu1      = (const float*)d_in[12];
    const float* Wm1      = (const float*)d_in[13];
    const float* Wm2      = (const float*)d_in[14];
    const float* Wm3      = (const float*)d_in[15];
    const float* Wd0      = (const float*)d_in[16];
    const float* Wd1      = (const float*)d_in[17];
    const float* Wt0      = (const float*)d_in[18];
    const float* Wt1      = (const float*)d_in[19];
    const float* Wq       = (const float*)d_in[20];
    const float* wqml     = (const float*)d_in[21];
    const float* Wo       = (const float*)d_in[22];
    const float* bo       = (const float*)d_in[23];

    float* out0 = (float*)d_out;
    float* outS = out0 + Nn;
    float* outV = outS + Nn * C0;

    static bool attr_done = false;
    size_t smem_pre  = (4096 + 1024 + 16384 + 4096 + 8 * 160) * sizeof(float);
    size_t smem_edge = (512 + 4096 + 18432 + 12 * (EPB * 128 + 544)) * sizeof(float);
    size_t smem_post = (10240 + 4096 + 16384 + 4096 + 512 + 24 + 24 + 8 + 8 * 712) * sizeof(float);
    if (!attr_done) {
        cudaFuncSetAttribute(node_pre_kernel,  cudaFuncAttributeMaxDynamicSharedMemorySize, (int)smem_pre);
        cudaFuncSetAttribute(edge_kernel,      cudaFuncAttributeMaxDynamicSharedMemorySize, (int)smem_edge);
        cudaFuncSetAttribute(node_post_kernel, cudaFuncAttributeMaxDynamicSharedMemorySize, (int)smem_post);
        attr_done = true;
    }

    zero_agg_kernel<<<1024, 256>>>();
    node_pre_kernel<<<148, 256, smem_pre>>>(s_in, v_in, species, Wskip0, Wskip1, Wu0, Wu1);
    edge_kernel<<<148, 384, smem_edge>>>(radial, Y0, Y1, senders, receivers, Wm1, Wm2, Wm3);
    node_post_kernel<<<148, 256, smem_post>>>(x_node, Wd0, Wd1, Wt0, Wt1, Wq, wqml, Wo, bo,
                                              out0, outS, outV);
}

// round 3
// speedup vs baseline: 1.1449x; 1.1449x over previous
#include <cuda_runtime.h>
#include <math.h>

#define Nn 8192
#define Ee 131072
#define C0 64
#define C1 32
#define NSs 160     // 2*C0 + C1
#define NVv 128     // C0 + 2*C1
#define EPB 8       // edges per warp batch
#define NPAIR 4     // EPB/2

typedef unsigned long long ull;

// ---------------- static device scratch ----------------
__device__ float g_s[Nn * C0];
__device__ float g_v[Nn * C1 * 3];
__device__ float g_skip_s[Nn * C0];
__device__ float g_skip_v[Nn * C1 * 3];
__device__ float g_agg_s[Nn * NSs];
__device__ float g_agg_v[Nn * NVv * 3];

__device__ __forceinline__ float silu_f(float x) {
    return __fdividef(x, 1.0f + __expf(-x));
}

// packed fp32x2 helpers (sm_100a): bit-exact dual fp32 FMA
__device__ __forceinline__ ull pack2(float x, float y) {
    ull r; asm("mov.b64 %0, {%1, %2};" : "=l"(r) : "f"(x), "f"(y)); return r;
}
__device__ __forceinline__ void unpack2(ull v, float& x, float& y) {
    asm("mov.b64 {%0, %1}, %2;" : "=f"(x), "=f"(y) : "l"(v));
}
__device__ __forceinline__ ull fma2(ull a, ull b, ull c) {
    ull d; asm("fma.rn.f32x2 %0, %1, %2, %3;" : "=l"(d) : "l"(a), "l"(b), "l"(c)); return d;
}

// ---------------- kernel 0: zero aggregation buffers ----------------
__global__ void zero_agg_kernel() {
    long i = (long)blockIdx.x * blockDim.x + threadIdx.x;
    long stride = (long)gridDim.x * blockDim.x;
    float4* a = (float4*)g_agg_s;
    long na = (long)Nn * NSs / 4;
    for (long j = i; j < na; j += stride) a[j] = make_float4(0.f, 0.f, 0.f, 0.f);
    float4* b = (float4*)g_agg_v;
    long nb = (long)Nn * NVv * 3 / 4;
    for (long j = i; j < nb; j += stride) b[j] = make_float4(0.f, 0.f, 0.f, 0.f);
}

// ---------------- kernel 1: node pre (Wu0/Wu1 + skips) ----------------
__global__ void __launch_bounds__(256) node_pre_kernel(
    const float* __restrict__ s_in, const float* __restrict__ v_in,
    const int* __restrict__ species,
    const float* __restrict__ Wskip0, const float* __restrict__ Wskip1,
    const float* __restrict__ Wu0, const float* __restrict__ Wu1)
{
    extern __shared__ float sm[];
    float* sWu0 = sm;                  // 4096
    float* sWu1 = sWu0 + 4096;         // 1024
    float* sWs0 = sWu1 + 1024;         // 16384
    float* sWs1 = sWs0 + 16384;        // 4096
    float* bufs = sWs1 + 4096;         // 8 warps * 160

    int tid = threadIdx.x;
    for (int i = tid; i < 4096;  i += blockDim.x) sWu0[i] = Wu0[i];
    for (int i = tid; i < 1024;  i += blockDim.x) sWu1[i] = Wu1[i];
    for (int i = tid; i < 16384; i += blockDim.x) sWs0[i] = Wskip0[i];
    for (int i = tid; i < 4096;  i += blockDim.x) sWs1[i] = Wskip1[i];
    __syncthreads();

    int w = tid >> 5, lane = tid & 31;
    float* sb = bufs + w * 160;
    float* vb = sb + 64;
    int warpsTotal = gridDim.x * 8;

    for (int n = blockIdx.x * 8 + w; n < Nn; n += warpsTotal) {
        sb[lane]      = s_in[n * 64 + lane];
        sb[lane + 32] = s_in[n * 64 + lane + 32];
        vb[lane]      = v_in[n * 96 + lane];
        vb[lane + 32] = v_in[n * 96 + lane + 32];
        vb[lane + 64] = v_in[n * 96 + lane + 64];
        __syncwarp();
        int sp = species[n];
        const float* Ws0 = sWs0 + sp * 4096;
        const float* Ws1 = sWs1 + sp * 1024;

        float a0 = 0.f, a1 = 0.f, b0 = 0.f, b1 = 0.f;
        #pragma unroll 8
        for (int c = 0; c < 64; c++) {
            float x = sb[c];
            a0 = fmaf(x, sWu0[c * 64 + lane],      a0);
            a1 = fmaf(x, sWu0[c * 64 + lane + 32], a1);
            b0 = fmaf(x, Ws0[c * 64 + lane],       b0);
            b1 = fmaf(x, Ws0[c * 64 + lane + 32],  b1);
        }
        g_s[n * 64 + lane]      = a0;
        g_s[n * 64 + lane + 32] = a1;
        g_skip_s[n * 64 + lane]      = b0;
        g_skip_s[n * 64 + lane + 32] = b1;

        float u0 = 0.f, u1 = 0.f, u2 = 0.f, k0 = 0.f, k1 = 0.f, k2 = 0.f;
        #pragma unroll 8
        for (int c = 0; c < 32; c++) {
            float wu = sWu1[c * 32 + lane];
            float wk = Ws1[c * 32 + lane];
            float x0 = vb[c * 3], x1 = vb[c * 3 + 1], x2 = vb[c * 3 + 2];
            u0 = fmaf(x0, wu, u0); u1 = fmaf(x1, wu, u1); u2 = fmaf(x2, wu, u2);
            k0 = fmaf(x0, wk, k0); k1 = fmaf(x1, wk, k1); k2 = fmaf(x2, wk, k2);
        }
        g_v[n * 96 + lane * 3]     = u0;
        g_v[n * 96 + lane * 3 + 1] = u1;
        g_v[n * 96 + lane * 3 + 2] = u2;
        g_skip_v[n * 96 + lane * 3]     = k0;
        g_skip_v[n * 96 + lane * 3 + 1] = k1;
        g_skip_v[n * 96 + lane * 3 + 2] = k2;
        __syncwarp();
    }
}

// ---------------- kernel 2: fused edge MLP (fp32x2 packed) + scatter ----------------
// h1/h2 stored as per-pair float2: index [p*64 + c] holds {h[2p][c], h[2p+1][c]}
__global__ void __launch_bounds__(384) edge_kernel(
    const float* __restrict__ radial, const float* __restrict__ Y0,
    const float* __restrict__ Y1,
    const int* __restrict__ senders, const int* __restrict__ receivers,
    const float* __restrict__ Wm1, const float* __restrict__ Wm2,
    const float* __restrict__ Wm3)
{
    extern __shared__ float sm[];
    float* sWm1 = sm;                 // 512
    float* sWm2 = sWm1 + 512;         // 4096
    float* sWm3 = sWm2 + 4096;        // 18432
    float* wb   = sWm3 + 18432;

    int tid = threadIdx.x, w = tid >> 5, lane = tid & 31;
    for (int i = tid; i < 512;   i += blockDim.x) sWm1[i] = Wm1[i];
    for (int i = tid; i < 4096;  i += blockDim.x) sWm2[i] = Wm2[i];
    for (int i = tid; i < 18432; i += blockDim.x) sWm3[i] = Wm3[i];
    __syncthreads();

    const int perW = 512 + 512 + 544;   // h1(pairs) + h2(pairs) + msg
    float* h1f = wb + w * perW;
    float* h2f = h1f + 512;
    float* msg = h2f + 512;
    ull* h1u = (ull*)h1f;
    ull* h2u = (ull*)h2f;

    int nwarps = gridDim.x * 12;
    int gw = blockIdx.x * 12 + w;
    const float inv_s3 = 0.57735026918962576f;

    for (int e0 = gw * EPB; e0 < Ee; e0 += nwarps * EPB) {
        // ---- layer 1: h1 = silu(radial @ Wm1), write per-pair float2 ----
        #pragma unroll
        for (int p = 0; p < NPAIR; p++) {
            float sv[2][2];
            #pragma unroll
            for (int hh = 0; hh < 2; hh++) {
                int e = e0 + 2 * p + hh;
                float rv = (lane < 8) ? radial[e * 8 + lane] : 0.f;
                float a0 = 0.f, a1 = 0.f;
                #pragma unroll
                for (int k = 0; k < 8; k++) {
                    float rk = __shfl_sync(0xffffffffu, rv, k);
                    a0 = fmaf(rk, sWm1[k * 64 + lane],      a0);
                    a1 = fmaf(rk, sWm1[k * 64 + lane + 32], a1);
                }
                sv[hh][0] = silu_f(a0);
                sv[hh][1] = silu_f(a1);
            }
            h1u[p * 64 + lane]      = pack2(sv[0][0], sv[1][0]);
            h1u[p * 64 + lane + 32] = pack2(sv[0][1], sv[1][1]);
        }
        __syncwarp();

        // ---- layer 2: h2 = silu(h1 @ Wm2), packed over edge pairs ----
        {
            ull acc0[NPAIR], acc1[NPAIR];
            #pragma unroll
            for (int p = 0; p < NPAIR; p++) { acc0[p] = 0ull; acc1[p] = 0ull; }
            for (int k = 0; k < 64; k++) {
                float w0 = sWm2[k * 64 + lane];
                float w1 = sWm2[k * 64 + lane + 32];
                ull w0p = pack2(w0, w0);
                ull w1p = pack2(w1, w1);
                #pragma unroll
                for (int p = 0; p < NPAIR; p++) {
                    ull hp = h1u[p * 64 + k];
                    acc0[p] = fma2(hp, w0p, acc0[p]);
                    acc1[p] = fma2(hp, w1p, acc1[p]);
                }
            }
            #pragma unroll
            for (int p = 0; p < NPAIR; p++) {
                float x, y;
                unpack2(acc0[p], x, y);
                h2u[p * 64 + lane] = pack2(silu_f(x), silu_f(y));
                unpack2(acc1[p], x, y);
                h2u[p * 64 + lane + 32] = pack2(silu_f(x), silu_f(y));
            }
        }
        __syncwarp();

        // ---- layer 3: mix = h2 @ Wm3 (lane owns cols lane+32r), packed pairs ----
        ull m2[NPAIR * 9];
        #pragma unroll
        for (int i = 0; i < NPAIR * 9; i++) m2[i] = 0ull;

        for (int k = 0; k < 64; k++) {
            ull hp[NPAIR];
            #pragma unroll
            for (int p = 0; p < NPAIR; p++) hp[p] = h2u[p * 64 + k];
            #pragma unroll
            for (int r = 0; r < 9; r++) {
                float wv = sWm3[k * 288 + lane + 32 * r];
                ull wp = pack2(wv, wv);
                #pragma unroll
                for (int p = 0; p < NPAIR; p++)
                    m2[p * 9 + r] = fma2(hp[p], wp, m2[p * 9 + r]);
            }
        }

        // ---- messages + scatter, edge by edge ----
        #pragma unroll
        for (int t = 0; t < EPB; t++) {
            int pp = t >> 1, hh = t & 1;
            float mr[9];
            #pragma unroll
            for (int r = 0; r < 9; r++) {
                float lo, hi;
                unpack2(m2[pp * 9 + r], lo, hi);
                mr[r] = hh ? hi : lo;
            }
            int e = e0 + t;
            int snd = senders[e];
            int rcv = receivers[e];
            float m0  = g_s[snd * 64 + lane];
            float m1  = g_s[snd * 64 + lane + 32];
            float mv0 = g_v[snd * 96 + lane * 3];
            float mv1 = g_v[snd * 96 + lane * 3 + 1];
            float mv2 = g_v[snd * 96 + lane * 3 + 2];
            float y0  = Y0[e];
            float y10 = Y1[e * 3], y11 = Y1[e * 3 + 1], y12 = Y1[e * 3 + 2];
            float dot = (mv0 * y10 + mv1 * y11 + mv2 * y12) * inv_s3;

            msg[lane]       = m0 * mr[0];
            msg[32 + lane]  = m1 * mr[1];
            msg[64 + lane]  = m0 * y0 * mr[2];
            msg[96 + lane]  = m1 * y0 * mr[3];
            msg[128 + lane] = dot * mr[4];
            int b0 = 160 + lane * 3;
            msg[b0]     = mv0 * mr[5];
            msg[b0 + 1] = mv1 * mr[5];
            msg[b0 + 2] = mv2 * mr[5];
            int b1 = 160 + (32 + lane) * 3;
            float f6 = m0 * mr[6];
            msg[b1]     = f6 * y10;
            msg[b1 + 1] = f6 * y11;
            msg[b1 + 2] = f6 * y12;
            int b2 = 160 + (64 + lane) * 3;
            float f7 = m1 * mr[7];
            msg[b2]     = f7 * y10;
            msg[b2 + 1] = f7 * y11;
            msg[b2 + 2] = f7 * y12;
            int b3 = 160 + (96 + lane) * 3;
            float f8 = y0 * mr[8];
            msg[b3]     = mv0 * f8;
            msg[b3 + 1] = mv1 * f8;
            msg[b3 + 2] = mv2 * f8;
            __syncwarp();

            float* aggs = g_agg_s + (long)rcv * NSs;
            float* aggv = g_agg_v + (long)rcv * (NVv * 3);
            const float4* m4 = (const float4*)msg;
            #pragma unroll
            for (int gi = 0; gi < 5; gi++) {
                int g = lane + gi * 32;
                if (g < 136) {
                    float4 vv = m4[g];
                    float* p = (g < 40) ? (aggs + 4 * g) : (aggv + 4 * (g - 40));
                    asm volatile("red.global.add.v4.f32 [%0], {%1, %2, %3, %4};"
                                 :: "l"(p), "f"(vv.x), "f"(vv.y), "f"(vv.z), "f"(vv.w)
                                 : "memory");
                }
            }
            __syncwarp();
        }
    }
}

// ---------------- kernel 3: node post (512 threads for occupancy) ----------------
__global__ void __launch_bounds__(512) node_post_kernel(
    const float* __restrict__ x_node,
    const float* __restrict__ Wd0, const float* __restrict__ Wd1,
    const float* __restrict__ Wt0, const float* __restrict__ Wt1,
    const float* __restrict__ Wq,  const float* __restrict__ wqml,
    const float* __restrict__ Wo,  const float* __restrict__ bo,
    float* __restrict__ out0, float* __restrict__ outS, float* __restrict__ outV)
{
    extern __shared__ float sm[];
    float* sWd0 = sm;                  // 10240
    float* sWd1 = sWd0 + 10240;        // 4096
    float* sWt0 = sWd1 + 4096;         // 16384
    float* sWt1 = sWt0 + 16384;        // 4096
    float* sWq  = sWt1 + 4096;         // 512
    float* cw   = sWq  + 512;          // 24
    float* sw_  = cw   + 24;           // 24
    float* sWo  = sw_  + 24;           // 8
    float* bufs = sWo  + 8;            // 16 warps * 712

    int tid = threadIdx.x;
    for (int i = tid; i < 10240; i += blockDim.x) sWd0[i] = Wd0[i];
    for (int i = tid; i < 4096;  i += blockDim.x) sWd1[i] = Wd1[i];
    for (int i = tid; i < 16384; i += blockDim.x) sWt0[i] = Wt0[i];
    for (int i = tid; i < 4096;  i += blockDim.x) sWt1[i] = Wt1[i];
    for (int i = tid; i < 512;   i += blockDim.x) sWq[i]  = Wq[i];
    if (tid < 24) {
        float ang = 0.5f * wqml[tid];
        cw[tid]  = cosf(ang);
        sw_[tid] = sinf(ang);
    }
    if (tid < 8) sWo[tid] = Wo[tid];
    __syncthreads();

    int w = tid >> 5, lane = tid & 31;
    float* asr  = bufs + w * 712;   // 160
    float* avr  = asr + 160;        // 384
    float* srow = avr + 384;        // 64
    float* vrow = srow + 64;        // 96
    float* frow = vrow + 96;        // 8
    const float inv16 = 1.0f / 16.0f;
    float bo0 = bo[0];
    int warpsTotal = gridDim.x * 16;

    for (int n = blockIdx.x * 16 + w; n < Nn; n += warpsTotal) {
        #pragma unroll
        for (int i = 0; i < 5; i++)  asr[lane + 32 * i] = g_agg_s[(long)n * 160 + lane + 32 * i];
        #pragma unroll
        for (int i = 0; i < 12; i++) avr[lane + 32 * i] = g_agg_v[(long)n * 384 + lane + 32 * i];
        __syncwarp();

        // s1 = agg_s @ Wd0 / 16
        float s1a = 0.f, s1b = 0.f;
        #pragma unroll 4
        for (int c = 0; c < 160; c++) {
            float x = asr[c];
            s1a = fmaf(x, sWd0[c * 64 + lane],      s1a);
            s1b = fmaf(x, sWd0[c * 64 + lane + 32], s1b);
        }
        s1a *= inv16; s1b *= inv16;

        // v1 = agg_v @ Wd1 / 16
        float v10 = 0.f, v11 = 0.f, v12 = 0.f;
        #pragma unroll 4
        for (int c = 0; c < 128; c++) {
            float wv = sWd1[c * 32 + lane];
            v10 = fmaf(avr[c * 3],     wv, v10);
            v11 = fmaf(avr[c * 3 + 1], wv, v11);
            v12 = fmaf(avr[c * 3 + 2], wv, v12);
        }
        v10 *= inv16; v11 *= inv16; v12 *= inv16;

        srow[lane] = s1a; srow[lane + 32] = s1b;
        vrow[lane * 3] = v10; vrow[lane * 3 + 1] = v11; vrow[lane * 3 + 2] = v12;
        __syncwarp();

        float xv[4];
        #pragma unroll
        for (int a = 0; a < 4; a++) xv[a] = x_node[n * 4 + a];

        // s2 = (x ⊗ s1) @ Wt0
        float o0 = 0.f, o1 = 0.f;
        #pragma unroll
        for (int a = 0; a < 4; a++) {
            float xa = xv[a];
            #pragma unroll 4
            for (int c = 0; c < 64; c++) {
                float f = xa * srow[c];
                o0 = fmaf(f, sWt0[(a * 64 + c) * 64 + lane],      o0);
                o1 = fmaf(f, sWt0[(a * 64 + c) * 64 + lane + 32], o1);
            }
        }
        // v2 = (x ⊗ v1) @ Wt1
        float p0 = 0.f, p1 = 0.f, p2 = 0.f;
        #pragma unroll
        for (int a = 0; a < 4; a++) {
            float xa = xv[a];
            #pragma unroll 4
            for (int c = 0; c < 32; c++) {
                float wt = sWt1[(a * 32 + c) * 32 + lane];
                p0 = fmaf(xa * vrow[c * 3],     wt, p0);
                p1 = fmaf(xa * vrow[c * 3 + 1], wt, p1);
                p2 = fmaf(xa * vrow[c * 3 + 2], wt, p2);
            }
        }

        float sf0 = o0 + g_skip_s[n * 64 + lane];
        float sf1 = o1 + g_skip_s[n * 64 + lane + 32];
        outS[n * 64 + lane]      = sf0;
        outS[n * 64 + lane + 32] = sf1;
        outV[n * 96 + lane * 3]     = p0 + g_skip_v[n * 96 + lane * 3];
        outV[n * 96 + lane * 3 + 1] = p1 + g_skip_v[n * 96 + lane * 3 + 1];
        outV[n * 96 + lane * 3 + 2] = p2 + g_skip_v[n * 96 + lane * 3 + 2];

        // feats = s_final @ Wq
        __syncwarp();
        srow[lane] = sf0; srow[lane + 32] = sf1;
        __syncwarp();
        if (lane < 8) {
            float f = 0.f;
            #pragma unroll 8
            for (int c = 0; c < 64; c++) f = fmaf(srow[c], sWq[c * 8 + lane], f);
            frow[lane] = f;
        }
        __syncwarp();

        // ---- quantum circuit: idx = lane*8 + l; qubit q <-> idx bit (7-q) ----
        float cs[8], sn[8];
        #pragma unroll
        for (int q = 0; q < 8; q++) {
            float a = 0.5f * frow[q];
            __sincosf(a, &sn[q], &cs[q]);
        }
        float lf = 1.f;
        #pragma unroll
        for (int j = 0; j < 5; j++) {
            int q = 4 - j;
            lf *= ((lane >> j) & 1) ? sn[q] : cs[q];
        }
        float amp[8];
        #pragma unroll
        for (int l = 0; l < 8; l++) {
            float f = lf;
            f *= (l & 4) ? sn[5] : cs[5];
            f *= (l & 2) ? sn[6] : cs[6];
            f *= (l & 1) ? sn[7] : cs[7];
            amp[l] = f;
        }

        #pragma unroll
        for (int L = 0; L < 3; L++) {
            #pragma unroll
            for (int q = 0; q < 8; q++) {
                float c = cw[L * 8 + q], s = sw_[L * 8 + q];
                const int b = 7 - q;
                if (b >= 3) {
                    const int m = 1 << (b - 3);
                    int bit = (lane >> (b - 3)) & 1;
                    #pragma unroll
                    for (int l = 0; l < 8; l++) {
                        float p = __shfl_xor_sync(0xffffffffu, amp[l], m);
                        amp[l] = bit ? fmaf(s, p, c * amp[l]) : (c * amp[l] - s * p);
                    }
                } else {
                    const int tm = 1 << b;
                    #pragma unroll
                    for (int l = 0; l < 8; l++) {
                        if (!(l & tm)) {
                            float a0 = amp[l], a1 = amp[l | tm];
                            amp[l]      = c * a0 - s * a1;
                            amp[l | tm] = fmaf(s, a0, c * a1);
                        }
                    }
                }
            }
            #pragma unroll
            for (int q = 0; q < 8; q++) {
                const int bc = 7 - q;
                const int bt = 7 - ((q + 1) & 7);
                if (bt >= 3) {
                    const int m = 1 << (bt - 3);
                    #pragma unroll
                    for (int l = 0; l < 8; l++) {
                        float p = __shfl_xor_sync(0xffffffffu, amp[l], m);
                        int ctrl = (bc >= 3) ? ((lane >> (bc - 3)) & 1) : ((l >> bc) & 1);
                        amp[l] = ctrl ? p : amp[l];
                    }
                } else {
                    const int tm = 1 << bt;
                    if (bc >= 3) {
                        int ctrl = (lane >> (bc - 3)) & 1;
                        #pragma unroll
                        for (int l = 0; l < 8; l++) {
                            if (!(l & tm)) {
                                float a = amp[l], bb = amp[l | tm];
                                amp[l]      = ctrl ? bb : a;
                                amp[l | tm] = ctrl ? a : bb;
                            }
                        }
                    } else {
                        #pragma unroll
                        for (int l = 0; l < 8; l++) {
                            if (!(l & tm) && ((l >> bc) & 1)) {
                                float tmp = amp[l];
                                amp[l] = amp[l | tm];
                                amp[l | tm] = tmp;
                            }
                        }
                    }
                }
            }
        }

        float tsum = 0.f, tb0 = 0.f, tb1 = 0.f, tb2 = 0.f;
        #pragma unroll
        for (int l = 0; l < 8; l++) {
            float p = amp[l] * amp[l];
            tsum += p;
            tb0 += (l & 1) ? -p : p;
            tb1 += (l & 2) ? -p : p;
            tb2 += (l & 4) ? -p : p;
        }
        float lanesum = 0.f;
        #pragma unroll
        for (int q = 0; q < 5; q++) {
            float sgn = ((lane >> (4 - q)) & 1) ? -1.f : 1.f;
            lanesum = fmaf(sgn * sWo[q], 1.f, lanesum);
        }
        float op = sWo[7] * tb0 + sWo[6] * tb1 + sWo[5] * tb2 + tsum * lanesum;
        #pragma unroll
        for (int o = 16; o > 0; o >>= 1)
            op += __shfl_xor_sync(0xffffffffu, op, o);
        if (lane == 0) out0[n] = op + bo0;
        __syncwarp();
    }
}

// ---------------- launch ----------------
extern "C" void kernel_launch(void* const* d_in, const int* in_sizes, int n_in,
                              void* d_out, int out_size) {
    const float* s_in     = (const float*)d_in[0];
    const float* v_in     = (const float*)d_in[1];
    const float* x_node   = (const float*)d_in[2];
    const float* radial   = (const float*)d_in[3];
    const float* Y0       = (const float*)d_in[4];
    const float* Y1       = (const float*)d_in[5];
    const int*   species  = (const int*)d_in[6];
    const int*   senders  = (const int*)d_in[7];
    const int*   receivers= (const int*)d_in[8];
    const float* Wskip0   = (const float*)d_in[9];
    const float* Wskip1   = (const float*)d_in[10];
    const float* Wu0      = (const float*)d_in[11];
    const float* Wu1      = (const float*)d_in[12];
    const float* Wm1      = (const float*)d_in[13];
    const float* Wm2      = (const float*)d_in[14];
    const float* Wm3      = (const float*)d_in[15];
    const float* Wd0      = (const float*)d_in[16];
    const float* Wd1      = (const float*)d_in[17];
    const float* Wt0      = (const float*)d_in[18];
    const float* Wt1      = (const float*)d_in[19];
    const float* Wq       = (const float*)d_in[20];
    const float* wqml     = (const float*)d_in[21];
    const float* Wo       = (const float*)d_in[22];
    const float* bo       = (const float*)d_in[23];

    float* out0 = (float*)d_out;
    float* outS = out0 + Nn;
    float* outV = outS + Nn * C0;

    static bool attr_done = false;
    size_t smem_pre  = (4096 + 1024 + 16384 + 4096 + 8 * 160) * sizeof(float);
    size_t smem_edge = (512 + 4096 + 18432 + 12 * (512 + 512 + 544)) * sizeof(float);
    size_t smem_post = (10240 + 4096 + 16384 + 4096 + 512 + 24 + 24 + 8 + 16 * 712) * sizeof(float);
    if (!attr_done) {
        cudaFuncSetAttribute(node_pre_kernel,  cudaFuncAttributeMaxDynamicSharedMemorySize, (int)smem_pre);
        cudaFuncSetAttribute(edge_kernel,      cudaFuncAttributeMaxDynamicSharedMemorySize, (int)smem_edge);
        cudaFuncSetAttribute(node_post_kernel, cudaFuncAttributeMaxDynamicSharedMemorySize, (int)smem_post);
        attr_done = true;
    }

    zero_agg_kernel<<<1024, 256>>>();
    node_pre_kernel<<<148, 256, smem_pre>>>(s_in, v_in, species, Wskip0, Wskip1, Wu0, Wu1);
    edge_kernel<<<148, 384, smem_edge>>>(radial, Y0, Y1, senders, receivers, Wm1, Wm2, Wm3);
    node_post_kernel<<<148, 512, smem_post>>>(x_node, Wd0, Wd1, Wt0, Wt1, Wq, wqml, Wo, bo,
                                              out0, outS, outV);
}